// round 3
// baseline (speedup 1.0000x reference)
#include <cuda_runtime.h>
#include <cuda_bf16.h>

#define FULL_MASK 0xFFFFFFFFu

// One warp per ray. S (=192) must be a multiple of 32 (it is).
// Transmittance cumprod done as: per-32-chunk warp inclusive scan product
// (shfl_up) converted to exclusive, times a running cross-chunk carry.
__global__ void __launch_bounds__(256) nerf_render_kernel(
    const float* __restrict__ rgb,     // [N, S, 3]
    const float* __restrict__ sigma,   // [N, S]
    const float* __restrict__ z_vals,  // [N, S]
    const float* __restrict__ rays_d,  // [N, 3]
    float* __restrict__ out,           // flattened 7-tuple
    int N, int S)
{
    const int warp_id = (int)((blockIdx.x * blockDim.x + threadIdx.x) >> 5);
    const int lane    = threadIdx.x & 31;
    if (warp_id >= N) return;
    const int ray = warp_id;

    // Output layout (tuple order, each flattened):
    // rgb_map[3N] | depth[N] | acc[N] | weights[N*S] | disp[N] | trans[N*S] | alpha[N*S]
    const size_t NS = (size_t)N * (size_t)S;
    float* out_rgb   = out;
    float* out_depth = out + (size_t)3 * N;
    float* out_acc   = out + (size_t)4 * N;
    float* out_w     = out + (size_t)5 * N;
    float* out_disp  = out + (size_t)5 * N + NS;
    float* out_trans = out + (size_t)6 * N + NS;
    float* out_alpha = out + (size_t)6 * N + 2 * NS;

    // ||rays_d|| (redundant per-lane load; 12B hits same cache line)
    const float dx = rays_d[ray * 3 + 0];
    const float dy = rays_d[ray * 3 + 1];
    const float dz = rays_d[ray * 3 + 2];
    const float norm = sqrtf(dx * dx + dy * dy + dz * dz);

    const float* zr = z_vals + (size_t)ray * S;
    const float* sr = sigma  + (size_t)ray * S;
    const float* cr = rgb    + (size_t)ray * S * 3;
    float* wr = out_w     + (size_t)ray * S;
    float* tr = out_trans + (size_t)ray * S;
    float* ar = out_alpha + (size_t)ray * S;

    float carry = 1.0f;            // prod of (1-alpha) over all previous chunks
    float accR = 0.f, accG = 0.f, accB = 0.f, accD = 0.f, accA = 0.f;

    #pragma unroll
    for (int base = 0; base < 192; base += 32) {
        const int i = base + lane;

        const float z = zr[i];
        // dist_i = z[i+1]-z[i] for i<S-1, else 1e10; then * norm
        float dist;
        if (i == S - 1) {
            dist = 1e10f;
        } else {
            dist = zr[i + 1] - z;
        }
        dist *= norm;

        const float s = sr[i];
        const float x = fmaxf(s, 0.0f) * dist;
        const float alpha = 1.0f - expf(-x);
        const float t = 1.0f - alpha;   // survival factor

        // Warp inclusive prefix product of t
        float incl = t;
        #pragma unroll
        for (int off = 1; off < 32; off <<= 1) {
            float v = __shfl_up_sync(FULL_MASK, incl, off);
            if (lane >= off) incl *= v;
        }
        // Exclusive prefix
        float excl = __shfl_up_sync(FULL_MASK, incl, 1);
        if (lane == 0) excl = 1.0f;

        const float trans = carry * excl;
        carry *= __shfl_sync(FULL_MASK, incl, 31);

        const float w = alpha * trans;

        // rgb loads: stride-12B across lanes, 384B contiguous per chunk (L1-friendly)
        const float r = cr[i * 3 + 0];
        const float g = cr[i * 3 + 1];
        const float b = cr[i * 3 + 2];

        accR += w * r;
        accG += w * g;
        accB += w * b;
        accD += w * z;
        accA += w;

        // Coalesced [N,S] stores
        wr[i] = w;
        tr[i] = trans;
        ar[i] = alpha;
    }

    // Warp reduce the 5 scalars
    #pragma unroll
    for (int off = 16; off > 0; off >>= 1) {
        accR += __shfl_down_sync(FULL_MASK, accR, off);
        accG += __shfl_down_sync(FULL_MASK, accG, off);
        accB += __shfl_down_sync(FULL_MASK, accB, off);
        accD += __shfl_down_sync(FULL_MASK, accD, off);
        accA += __shfl_down_sync(FULL_MASK, accA, off);
    }

    if (lane == 0) {
        out_rgb[ray * 3 + 0] = accR;
        out_rgb[ray * 3 + 1] = accG;
        out_rgb[ray * 3 + 2] = accB;
        out_depth[ray] = accD;
        out_acc[ray]   = accA;
        out_disp[ray]  = 1.0f / fmaxf(1e-10f, accD / accA);
    }
}

extern "C" void kernel_launch(void* const* d_in, const int* in_sizes, int n_in,
                              void* d_out, int out_size) {
    const float* rgb    = (const float*)d_in[0];
    const float* sigma  = (const float*)d_in[1];
    const float* z_vals = (const float*)d_in[2];
    const float* rays_d = (const float*)d_in[3];
    float* out = (float*)d_out;

    const int N = in_sizes[3] / 3;          // 65536
    const int S = in_sizes[1] / N;          // 192

    const int threads = 256;                // 8 warps = 8 rays / block
    const int total_threads = N * 32;
    const int blocks = (total_threads + threads - 1) / threads;
    nerf_render_kernel<<<blocks, threads>>>(rgb, sigma, z_vals, rays_d, out, N, S);
}

// round 5
// speedup vs baseline: 1.2230x; 1.2230x over previous
#include <cuda_runtime.h>
#include <cuda_bf16.h>

#define FULL_MASK 0xFFFFFFFFu
#define NCHUNK 6           // S = 192 = 6 * 32

// One warp per ray. All loads front-batched (high MLP), the six 32-wide
// prefix-product scans run as independent interleaved shfl chains (6-way ILP),
// only the 6-step carry chain is sequential.
__global__ void __launch_bounds__(256) nerf_render_kernel(
    const float* __restrict__ rgb,     // [N, S, 3]
    const float* __restrict__ sigma,   // [N, S]
    const float* __restrict__ z_vals,  // [N, S]
    const float* __restrict__ rays_d,  // [N, 3]
    float* __restrict__ out,           // flattened 7-tuple
    int N)
{
    const int S = NCHUNK * 32;
    const int warp_id = (int)((blockIdx.x * blockDim.x + threadIdx.x) >> 5);
    const int lane    = threadIdx.x & 31;
    if (warp_id >= N) return;
    const int ray = warp_id;

    const size_t NS = (size_t)N * (size_t)S;
    float* out_rgb   = out;
    float* out_depth = out + (size_t)3 * N;
    float* out_acc   = out + (size_t)4 * N;
    float* out_w     = out + (size_t)5 * N;
    float* out_disp  = out + (size_t)5 * N + NS;
    float* out_trans = out + (size_t)6 * N + NS;
    float* out_alpha = out + (size_t)6 * N + 2 * NS;

    const float* zr  = z_vals + (size_t)ray * S;
    const float* sr  = sigma  + (size_t)ray * S;
    const float* crf = rgb    + (size_t)ray * S * 3;
    float* wr = out_w     + (size_t)ray * S;
    float* tr = out_trans + (size_t)ray * S;
    float* ar = out_alpha + (size_t)ray * S;

    // ---------------- Phase A: batch ALL global loads ----------------
    float z[NCHUNK], sg[NCHUNK];
    #pragma unroll
    for (int c = 0; c < NCHUNK; c++) {
        z[c]  = __ldcs(zr + c * 32 + lane);
        sg[c] = __ldcs(sr + c * 32 + lane);
    }
    // rgb: fully coalesced flat loads; v[c][j] = flat float (96c + lane + 32j)
    float v[NCHUNK][3];
    #pragma unroll
    for (int c = 0; c < NCHUNK; c++) {
        #pragma unroll
        for (int j = 0; j < 3; j++)
            v[c][j] = __ldcs(crf + c * 96 + lane + 32 * j);
    }
    const float dx = rays_d[ray * 3 + 0];
    const float dy = rays_d[ray * 3 + 1];
    const float dz = rays_d[ray * 3 + 2];
    const float norm = sqrtf(dx * dx + dy * dy + dz * dz);

    // Per-lane constant gather pattern for the flat rgb layout:
    // flat f = lane + 32j  ->  local sample s_j = f/3 (shfl source), channel c_j = f%3
    const int s0 = lane / 3,          ch0 = lane % 3;
    const int s1 = (lane + 32) / 3,   ch1 = (lane + 32) % 3;
    const int s2 = (lane + 64) / 3,   ch2 = (lane + 64) % 3;

    // ---------------- Phase B: alpha / survival per chunk ----------------
    float alpha[NCHUNK], incl[NCHUNK];
    #pragma unroll
    for (int c = 0; c < NCHUNK; c++) {
        // z_next: shift within chunk; lane 31 takes lane 0 of next chunk
        float znext = __shfl_down_sync(FULL_MASK, z[c], 1);
        if (c < NCHUNK - 1) {
            float nxt0 = __shfl_sync(FULL_MASK, z[c + 1], 0);
            if (lane == 31) znext = nxt0;
        }
        float dist_raw = (c == NCHUNK - 1 && lane == 31) ? 1e10f : (znext - z[c]);
        float x = fmaxf(sg[c], 0.0f) * (dist_raw * norm);
        alpha[c] = 1.0f - expf(-x);
        incl[c]  = 1.0f - alpha[c];     // survival factor; becomes inclusive scan
    }

    // ---------------- Phase C: 6 independent inclusive scans (ILP) ----------
    #pragma unroll
    for (int off = 1; off < 32; off <<= 1) {
        #pragma unroll
        for (int c = 0; c < NCHUNK; c++) {
            float t = __shfl_up_sync(FULL_MASK, incl[c], off);
            if (lane >= off) incl[c] *= t;
        }
    }

    // totals + exclusive
    float excl[NCHUNK], tot[NCHUNK];
    #pragma unroll
    for (int c = 0; c < NCHUNK; c++) {
        tot[c]  = __shfl_sync(FULL_MASK, incl[c], 31);
        excl[c] = __shfl_up_sync(FULL_MASK, incl[c], 1);
        if (lane == 0) excl[c] = 1.0f;
    }

    // ---------------- Phase D: carry chain (only sequential part) ----------
    float trans[NCHUNK];
    {
        float carry = 1.0f;
        #pragma unroll
        for (int c = 0; c < NCHUNK; c++) {
            trans[c] = carry * excl[c];
            carry *= tot[c];
        }
    }

    // ---------------- Phase E: weights, stores, accumulations --------------
    float accJ0 = 0.f, accJ1 = 0.f, accJ2 = 0.f;   // channel-tagged rgb accums
    float accD = 0.f, accA = 0.f;

    #pragma unroll
    for (int c = 0; c < NCHUNK; c++) {
        const float w = alpha[c] * trans[c];

        __stcs(wr + c * 32 + lane, w);
        __stcs(tr + c * 32 + lane, trans[c]);
        __stcs(ar + c * 32 + lane, alpha[c]);

        accD += w * z[c];
        accA += w;

        // gather weights for the flat rgb elements this lane owns
        accJ0 += __shfl_sync(FULL_MASK, w, s0) * v[c][0];
        accJ1 += __shfl_sync(FULL_MASK, w, s1) * v[c][1];
        accJ2 += __shfl_sync(FULL_MASK, w, s2) * v[c][2];
    }

    // route channel-tagged accumulators to R/G/B
    float accR = (ch0 == 0 ? accJ0 : 0.f) + (ch1 == 0 ? accJ1 : 0.f) + (ch2 == 0 ? accJ2 : 0.f);
    float accG = (ch0 == 1 ? accJ0 : 0.f) + (ch1 == 1 ? accJ1 : 0.f) + (ch2 == 1 ? accJ2 : 0.f);
    float accB = (ch0 == 2 ? accJ0 : 0.f) + (ch1 == 2 ? accJ1 : 0.f) + (ch2 == 2 ? accJ2 : 0.f);

    // warp reduce the 5 scalars
    #pragma unroll
    for (int off = 16; off > 0; off >>= 1) {
        accR += __shfl_down_sync(FULL_MASK, accR, off);
        accG += __shfl_down_sync(FULL_MASK, accG, off);
        accB += __shfl_down_sync(FULL_MASK, accB, off);
        accD += __shfl_down_sync(FULL_MASK, accD, off);
        accA += __shfl_down_sync(FULL_MASK, accA, off);
    }

    if (lane == 0) {
        out_rgb[ray * 3 + 0] = accR;
        out_rgb[ray * 3 + 1] = accG;
        out_rgb[ray * 3 + 2] = accB;
        out_depth[ray] = accD;
        out_acc[ray]   = accA;
        out_disp[ray]  = 1.0f / fmaxf(1e-10f, accD / accA);
    }
}

extern "C" void kernel_launch(void* const* d_in, const int* in_sizes, int n_in,
                              void* d_out, int out_size) {
    const float* rgb    = (const float*)d_in[0];
    const float* sigma  = (const float*)d_in[1];
    const float* z_vals = (const float*)d_in[2];
    const float* rays_d = (const float*)d_in[3];
    float* out = (float*)d_out;

    const int N = in_sizes[3] / 3;          // 65536

    const int threads = 256;                // 8 warps = 8 rays / block
    const int blocks = (N * 32) / threads;  // 8192
    nerf_render_kernel<<<blocks, threads>>>(rgb, sigma, z_vals, rays_d, out, N);
}